// round 14
// baseline (speedup 1.0000x reference)
#include <cuda_runtime.h>
#include <cuda_bf16.h>

// y[m] = 0.75 * sum_k( x[m,k] * wcs[k] ),  wcs[k] = sum_n weight[n,k]
// x: [M,K] fp32, weight: [N,K] fp32, out: [M,1] fp32.  M=K=N=8192.
// HBM-streaming: 512 MiB compulsory traffic; measured chip ceiling ~6.4 TB/s.
//
//  0) cudaMemsetAsync zeroes g_wcs (graph memset node)
//  1) fused kernel, 1184 blocks x 256 thr = EXACTLY 8 CTAs/SM (launch_bounds
//     forces <=32 regs so all blocks are co-resident -> barrier is safe):
//     Phase A: float2 colsum (proven R9 shape: 100% occ, 74-way atomic fan-in)
//     ticket barrier (monotonic counter: no reset, no cleanup, replay-safe)
//     Phase B: rowdot (proven R1 inner loop), rows strided by grid, wcs via ldcg

#define MM 8192
#define KK 8192
#define NN 8192
#define COL4 (KK / 4)   // 2048 float4 per row
#define COL2 (KK / 2)   // 4096 float2 per row

#define GRIDB   1184    // 148 SMs x 8 CTAs
#define THREADS 256
#define CHUNKS  74      // GRIDB*THREADS / COL2

__device__ float    g_wcs[KK];
__device__ unsigned g_bar = 0;   // monotonic ticket counter (never reset)

__global__ __launch_bounds__(THREADS, 8)
void fused_kernel(const float* __restrict__ x,
                  const float* __restrict__ weight,
                  float* __restrict__ out) {
    const int tid = threadIdx.x;
    const int gt  = blockIdx.x * THREADS + tid;   // 0 .. 303103

    // ---------------- Phase A: column-sum of weight (float2/thread) --------
    {
        const int col2  = gt & (COL2 - 1);                     // 0..4095
        const int chunk = gt >> 12;                            // 0..73
        const int r0 = (int)(((long long)chunk * NN) / CHUNKS);
        const int r1 = (int)(((long long)(chunk + 1) * NN) / CHUNKS);

        const float2* __restrict__ w2 = reinterpret_cast<const float2*>(weight) + col2;

        float2 acc = make_float2(0.f, 0.f);
#pragma unroll 8
        for (int r = r0; r < r1; ++r) {
            float2 v = __ldcs(w2 + (size_t)r * COL2);
            acc.x += v.x; acc.y += v.y;
        }
        const int col = col2 * 2;
        atomicAdd(&g_wcs[col + 0], acc.x);
        atomicAdd(&g_wcs[col + 1], acc.y);
    }

    // ---------------- ticket grid barrier (replay-safe, no reset) ----------
    __syncthreads();
    if (tid == 0) {
        __threadfence();
        unsigned t = atomicAdd(&g_bar, 1u);
        unsigned target = t - (t % GRIDB) + GRIDB;   // next multiple of GRIDB
        while ((int)(*(volatile unsigned*)&g_bar - target) < 0) { }
        __threadfence();
    }
    __syncthreads();

    // ---------------- Phase B: row dot products ----------------------------
    {
        const int lane = tid & 31;
        const int wid  = tid >> 5;
        __shared__ float warp_sums[THREADS / 32];

        for (int row = blockIdx.x; row < MM; row += GRIDB) {
            const float4* __restrict__ x4 =
                reinterpret_cast<const float4*>(x) + (size_t)row * COL4;
            const float4* __restrict__ w4 =
                reinterpret_cast<const float4*>(g_wcs);

            float acc = 0.0f;
#pragma unroll
            for (int i = 0; i < COL4 / THREADS; ++i) {   // 8 iterations
                const int idx = i * THREADS + tid;
                float4 xv = __ldcs(x4 + idx);
                float4 wv = __ldcg(w4 + idx);   // L2 (atomic results), skip L1
                acc = fmaf(xv.x, wv.x, acc);
                acc = fmaf(xv.y, wv.y, acc);
                acc = fmaf(xv.z, wv.z, acc);
                acc = fmaf(xv.w, wv.w, acc);
            }

#pragma unroll
            for (int off = 16; off > 0; off >>= 1)
                acc += __shfl_down_sync(0xFFFFFFFFu, acc, off);

            if (lane == 0) warp_sums[wid] = acc;
            __syncthreads();

            if (wid == 0) {
                float s = (lane < THREADS / 32) ? warp_sums[lane] : 0.0f;
#pragma unroll
                for (int off = 4; off > 0; off >>= 1)
                    s += __shfl_down_sync(0xFFFFFFFFu, s, off);
                if (lane == 0) out[row] = 0.75f * s;
            }
            __syncthreads();   // protect warp_sums reuse across row iterations
        }
    }
}

// ---------------------------------------------------------------- launcher
extern "C" void kernel_launch(void* const* d_in, const int* in_sizes, int n_in,
                              void* d_out, int out_size) {
    const float* x      = (const float*)d_in[0];
    const float* weight = (const float*)d_in[1];
    float* out = (float*)d_out;

    void* wcs_ptr = nullptr;
    cudaGetSymbolAddress(&wcs_ptr, g_wcs);
    cudaMemsetAsync(wcs_ptr, 0, KK * sizeof(float));   // graph memset node

    fused_kernel<<<GRIDB, THREADS>>>(x, weight, out);
}